// round 16
// baseline (speedup 1.0000x reference)
#include <cuda_runtime.h>
#include <cuda_bf16.h>
#include <math.h>

#define NNODES 50000
#define NEDGES 800000
#define NEG_SLOPE 0.2f

// ---------------- scratch (static device globals; no runtime allocation) ----
__device__ float g_feat[NNODES * 128];
__device__ float g_h[NNODES * 128];
__device__ float g_el[NNODES * 4];
__device__ float g_er[NNODES * 4];
__device__ int   g_rowptr[NNODES + 1];
__device__ int   g_idx64;

// ---------------- index dtype detection (tail scan) ---------------------------
__global__ void detect_idx_kernel(const int* __restrict__ words, int n_words) {
    __shared__ int any;
    if (threadIdx.x == 0) any = 0;
    __syncthreads();
    int base = n_words > 4096 ? (n_words - 4096) & ~1 : 0;
    int local = 0;
    for (int i = base + 2 * threadIdx.x + 1; i < n_words; i += 2 * blockDim.x)
        local |= words[i];
    if (local) atomicOr(&any, 1);
    __syncthreads();
    if (threadIdx.x == 0) g_idx64 = any ? 0 : 1;
}

__device__ __forceinline__ int load_idx(const void* p, int i, int is64) {
    if (is64) return (int)((const long long*)p)[i];
    return ((const int*)p)[i];
}

// ---------------- CSR row pointers from sorted dst ---------------------------
__global__ void __launch_bounds__(256) rowptr_kernel(const void* __restrict__ dst,
                                                     int n_nodes, int n_edges) {
    int n = blockIdx.x * blockDim.x + threadIdx.x;
    if (n > n_nodes) return;
    int is64 = g_idx64;
    int lo = 0, hi = n_edges;
    while (lo < hi) {
        int mid = (lo + hi) >> 1;
        if (load_idx(dst, mid, is64) < n) lo = mid + 1; else hi = mid;
    }
    g_rowptr[n] = lo;
}

// ---------------- tf32 helpers ------------------------------------------------
__device__ __forceinline__ float to_tf32(float x) {
    unsigned u;
    asm("cvt.rna.tf32.f32 %0, %1;" : "=r"(u) : "f"(x));
    return __uint_as_float(u);
}

__device__ __forceinline__ void mma_tf32(float* d, const unsigned* a, const unsigned* b) {
    asm volatile(
        "mma.sync.aligned.m16n8k8.row.col.f32.tf32.tf32.f32 "
        "{%0,%1,%2,%3}, {%4,%5,%6,%7}, {%8,%9}, {%0,%1,%2,%3};"
        : "+f"(d[0]), "+f"(d[1]), "+f"(d[2]), "+f"(d[3])
        : "r"(a[0]), "r"(a[1]), "r"(a[2]), "r"(a[3]), "r"(b[0]), "r"(b[1]));
}

// ---------------- tf32 tensor-core GEMM + fused el/er (R12 version) -----------
template<int K, int MOUT, int H>
__global__ void __launch_bounds__(256) gemm_tc_kernel(const float* __restrict__ A,
                                                      const float* __restrict__ W,
                                                      const float* __restrict__ al,
                                                      const float* __restrict__ ar,
                                                      float* __restrict__ C, int nrows) {
    constexpr int BM = 128, BK = 32;
    constexpr int AP = BM + 8;
    constexpr int BP = MOUT + 8;
    constexpr int WN = MOUT / 4;
    constexpr int NT = WN / 8;
    constexpr int MT = 4;

    __shared__ float As[BK * AP];
    __shared__ float Bs[BK * BP];
    __shared__ float elp[4][BM];
    __shared__ float erp[4][BM];

    int tid = threadIdx.x;
    int wid = tid >> 5;
    int lane = tid & 31;
    int wr = wid >> 2;
    int wc = wid & 3;
    int g = lane >> 2;
    int tig = lane & 3;
    int row0 = blockIdx.x * BM;
    int mwarp = wr * 64;

    float acc[MT][NT][4];
#pragma unroll
    for (int mt = 0; mt < MT; mt++)
#pragma unroll
        for (int nt = 0; nt < NT; nt++)
#pragma unroll
            for (int q = 0; q < 4; q++) acc[mt][nt][q] = 0.f;

    for (int kb = 0; kb < K; kb += BK) {
#pragma unroll
        for (int l = 0; l < (BM * BK) / (256 * 4); ++l) {
            int idx = (tid + l * 256) * 4;
            int r = idx / BK, c = idx % BK;
            float4 v = make_float4(0.f, 0.f, 0.f, 0.f);
            int gr = row0 + r;
            if (gr < nrows) v = *(const float4*)(A + (size_t)gr * K + kb + c);
            v.x = to_tf32(v.x); v.y = to_tf32(v.y); v.z = to_tf32(v.z); v.w = to_tf32(v.w);
            As[(c + 0) * AP + (r ^ ((((c + 0) >> 2) & 7) << 2))] = v.x;
            As[(c + 1) * AP + (r ^ ((((c + 1) >> 2) & 7) << 2))] = v.y;
            As[(c + 2) * AP + (r ^ ((((c + 2) >> 2) & 7) << 2))] = v.z;
            As[(c + 3) * AP + (r ^ ((((c + 3) >> 2) & 7) << 2))] = v.w;
        }
#pragma unroll
        for (int l = 0; l < (BK * MOUT) / (256 * 4); ++l) {
            int idx = (tid + l * 256) * 4;
            int r = idx / MOUT, c = idx % MOUT;
            float4 v = *(const float4*)(W + (size_t)(kb + r) * MOUT + c);
            v.x = to_tf32(v.x); v.y = to_tf32(v.y); v.z = to_tf32(v.z); v.w = to_tf32(v.w);
            *(float4*)&Bs[r * BP + c] = v;
        }
        __syncthreads();

#pragma unroll
        for (int ks = 0; ks < BK / 8; ks++) {
            int k0 = ks * 8;
            int ka = k0 + tig, kc = k0 + tig + 4;
            int sa = ((ka >> 2) & 7) << 2;
            int sc = ((kc >> 2) & 7) << 2;
            unsigned af[MT][4];
#pragma unroll
            for (int mt = 0; mt < MT; mt++) {
                int mb = mwarp + mt * 16;
                af[mt][0] = __float_as_uint(As[ka * AP + ((mb + g)     ^ sa)]);
                af[mt][1] = __float_as_uint(As[ka * AP + ((mb + g + 8) ^ sa)]);
                af[mt][2] = __float_as_uint(As[kc * AP + ((mb + g)     ^ sc)]);
                af[mt][3] = __float_as_uint(As[kc * AP + ((mb + g + 8) ^ sc)]);
            }
            unsigned bf[NT][2];
#pragma unroll
            for (int nt = 0; nt < NT; nt++) {
                int nb = wc * WN + nt * 8 + g;
                bf[nt][0] = __float_as_uint(Bs[ka * BP + nb]);
                bf[nt][1] = __float_as_uint(Bs[kc * BP + nb]);
            }
#pragma unroll
            for (int mt = 0; mt < MT; mt++)
#pragma unroll
                for (int nt = 0; nt < NT; nt++)
                    mma_tf32(acc[mt][nt], af[mt], bf[nt]);
        }
        __syncthreads();
    }

#pragma unroll
    for (int mt = 0; mt < MT; mt++) {
        int lr0 = mwarp + mt * 16 + g;
        int gr0 = row0 + lr0, gr1 = gr0 + 8;
        float sl0 = 0.f, sr0 = 0.f, sl1 = 0.f, sr1 = 0.f;
#pragma unroll
        for (int nt = 0; nt < NT; nt++) {
            int c = wc * WN + nt * 8 + 2 * tig;
            float a0 = al[c], a1 = al[c + 1];
            float r0 = ar[c], r1 = ar[c + 1];
            float* d = acc[mt][nt];
            sl0 += d[0] * a0 + d[1] * a1;  sr0 += d[0] * r0 + d[1] * r1;
            sl1 += d[2] * a0 + d[3] * a1;  sr1 += d[2] * r0 + d[3] * r1;
            if (gr0 < nrows) *(float2*)(C + (size_t)gr0 * MOUT + c) = make_float2(d[0], d[1]);
            if (gr1 < nrows) *(float2*)(C + (size_t)gr1 * MOUT + c) = make_float2(d[2], d[3]);
        }
#pragma unroll
        for (int off = 1; off <= 2; off <<= 1) {
            sl0 += __shfl_xor_sync(0xFFFFFFFFu, sl0, off);
            sr0 += __shfl_xor_sync(0xFFFFFFFFu, sr0, off);
            sl1 += __shfl_xor_sync(0xFFFFFFFFu, sl1, off);
            sr1 += __shfl_xor_sync(0xFFFFFFFFu, sr1, off);
        }
        if (tig == 0) {
            elp[wc][lr0] = sl0;  elp[wc][lr0 + 8] = sl1;
            erp[wc][lr0] = sr0;  erp[wc][lr0 + 8] = sr1;
        }
    }
    __syncthreads();
    if (tid < BM) {
        int gr = row0 + tid;
        if (gr < nrows) {
            if (H == 4) {
                *(float4*)(g_el + gr * 4) =
                    make_float4(elp[0][tid], elp[1][tid], elp[2][tid], elp[3][tid]);
                *(float4*)(g_er + gr * 4) =
                    make_float4(erp[0][tid], erp[1][tid], erp[2][tid], erp[3][tid]);
            } else {
                g_el[gr] = elp[0][tid] + elp[1][tid] + elp[2][tid] + elp[3][tid];
                g_er[gr] = erp[0][tid] + erp[1][tid] + erp[2][tid] + erp[3][tid];
            }
        }
    }
}

// ---------------- aggregation, H=4 D=32: two warps/node, FUSED edge weights ---
// Each lane owns head hh = lane>>3; weight exp(leaky(el[s]+er[dst])) is
// computed in-lane (4 extra warp-instrs/edge) instead of staged via g_w.
template<bool DO_ELU>
__global__ void __launch_bounds__(256) gat_agg128_kernel(const void* __restrict__ src,
                                                         const float* __restrict__ feat,
                                                         const float* __restrict__ bias,
                                                         float* __restrict__ out, int n_nodes) {
    __shared__ float4 s_acc[8][32];
    __shared__ float  s_den[8][32];

    int gw = (blockIdx.x * blockDim.x + threadIdx.x) >> 5;
    int wib = threadIdx.x >> 5;
    int lane = threadIdx.x & 31;
    int node = gw >> 1;
    int half = gw & 1;
    bool valid = node < n_nodes;
    int is64 = g_idx64;
    int hh = lane >> 3;

    float4 acc = make_float4(0.f, 0.f, 0.f, 0.f);
    float denom = 0.f;

    if (valid) {
        float er_h = g_er[node * 4 + hh];
        int start = g_rowptr[node];
        int end = g_rowptr[node + 1];
        int i = start + half;
        for (; i + 14 < end; i += 16) {
            int s[8]; float e8[8]; float4 f[8];
#pragma unroll
            for (int j = 0; j < 8; j++) s[j] = load_idx(src, i + 2 * j, is64);
#pragma unroll
            for (int j = 0; j < 8; j++) e8[j] = g_el[s[j] * 4 + hh];
#pragma unroll
            for (int j = 0; j < 8; j++)
                f[j] = *(const float4*)(feat + (size_t)s[j] * 128 + lane * 4);
#pragma unroll
            for (int j = 0; j < 8; j++) {
                float t = e8[j] + er_h;
                t = (t > 0.f) ? t : NEG_SLOPE * t;
                float w = __expf(t);
                denom += w;
                acc.x += w * f[j].x; acc.y += w * f[j].y;
                acc.z += w * f[j].z; acc.w += w * f[j].w;
            }
        }
        for (; i + 6 < end; i += 8) {
            int s[4]; float e4[4]; float4 f[4];
#pragma unroll
            for (int j = 0; j < 4; j++) s[j] = load_idx(src, i + 2 * j, is64);
#pragma unroll
            for (int j = 0; j < 4; j++) e4[j] = g_el[s[j] * 4 + hh];
#pragma unroll
            for (int j = 0; j < 4; j++)
                f[j] = *(const float4*)(feat + (size_t)s[j] * 128 + lane * 4);
#pragma unroll
            for (int j = 0; j < 4; j++) {
                float t = e4[j] + er_h;
                t = (t > 0.f) ? t : NEG_SLOPE * t;
                float w = __expf(t);
                denom += w;
                acc.x += w * f[j].x; acc.y += w * f[j].y;
                acc.z += w * f[j].z; acc.w += w * f[j].w;
            }
        }
        for (; i < end; i += 2) {
            int s = load_idx(src, i, is64);
            float t = g_el[s * 4 + hh] + er_h;
            t = (t > 0.f) ? t : NEG_SLOPE * t;
            float w = __expf(t);
            float4 f = *(const float4*)(feat + (size_t)s * 128 + lane * 4);
            denom += w;
            acc.x += w * f.x; acc.y += w * f.y; acc.z += w * f.z; acc.w += w * f.w;
        }
    }

    if (half == 1) { s_acc[wib][lane] = acc; s_den[wib][lane] = denom; }
    __syncthreads();

    if (valid && half == 0) {
        float4 p = s_acc[wib + 1][lane];
        acc.x += p.x; acc.y += p.y; acc.z += p.z; acc.w += p.w;
        denom += s_den[wib + 1][lane];

        float inv = 1.f / (denom + 1e-9f);
        float4 b4 = *(const float4*)(bias + lane * 4);
        float4 o;
        o.x = acc.x * inv + b4.x;
        o.y = acc.y * inv + b4.y;
        o.z = acc.z * inv + b4.z;
        o.w = acc.w * inv + b4.w;
        if (DO_ELU) {
            o.x = (o.x > 0.f) ? o.x : expm1f(o.x);
            o.y = (o.y > 0.f) ? o.y : expm1f(o.y);
            o.z = (o.z > 0.f) ? o.z : expm1f(o.z);
            o.w = (o.w > 0.f) ? o.w : expm1f(o.w);
        }
        *(float4*)(out + (size_t)node * 128 + lane * 4) = o;
    }
}

// ---------------- aggregation, H=1 D=64: two warps/node, FUSED edge weights ---
__global__ void __launch_bounds__(256) gat_agg64_kernel(const void* __restrict__ src,
                                                        const float* __restrict__ feat,
                                                        const float* __restrict__ bias,
                                                        float* __restrict__ out, int n_nodes) {
    __shared__ float2 s_acc[8][32];
    __shared__ float  s_den[8][32];

    int gw = (blockIdx.x * blockDim.x + threadIdx.x) >> 5;
    int wib = threadIdx.x >> 5;
    int lane = threadIdx.x & 31;
    int node = gw >> 1;
    int half = gw & 1;
    bool valid = node < n_nodes;
    int is64 = g_idx64;

    float2 acc = make_float2(0.f, 0.f);
    float denom = 0.f;

    if (valid) {
        float er_h = g_er[node];
        int start = g_rowptr[node];
        int end = g_rowptr[node + 1];
        int i = start + half;
        for (; i + 14 < end; i += 16) {
            int s[8]; float e8[8]; float2 f[8];
#pragma unroll
            for (int j = 0; j < 8; j++) s[j] = load_idx(src, i + 2 * j, is64);
#pragma unroll
            for (int j = 0; j < 8; j++) e8[j] = g_el[s[j]];
#pragma unroll
            for (int j = 0; j < 8; j++)
                f[j] = *(const float2*)(feat + (size_t)s[j] * 64 + lane * 2);
#pragma unroll
            for (int j = 0; j < 8; j++) {
                float t = e8[j] + er_h;
                t = (t > 0.f) ? t : NEG_SLOPE * t;
                float w = __expf(t);
                denom += w;
                acc.x += w * f[j].x; acc.y += w * f[j].y;
            }
        }
        for (; i + 6 < end; i += 8) {
            int s[4]; float e4[4]; float2 f[4];
#pragma unroll
            for (int j = 0; j < 4; j++) s[j] = load_idx(src, i + 2 * j, is64);
#pragma unroll
            for (int j = 0; j < 4; j++) e4[j] = g_el[s[j]];
#pragma unroll
            for (int j = 0; j < 4; j++)
                f[j] = *(const float2*)(feat + (size_t)s[j] * 64 + lane * 2);
#pragma unroll
            for (int j = 0; j < 4; j++) {
                float t = e4[j] + er_h;
                t = (t > 0.f) ? t : NEG_SLOPE * t;
                float w = __expf(t);
                denom += w;
                acc.x += w * f[j].x; acc.y += w * f[j].y;
            }
        }
        for (; i < end; i += 2) {
            int s = load_idx(src, i, is64);
            float t = g_el[s] + er_h;
            t = (t > 0.f) ? t : NEG_SLOPE * t;
            float w = __expf(t);
            float2 f = *(const float2*)(feat + (size_t)s * 64 + lane * 2);
            denom += w;
            acc.x += w * f.x; acc.y += w * f.y;
        }
    }

    if (half == 1) { s_acc[wib][lane] = acc; s_den[wib][lane] = denom; }
    __syncthreads();

    if (valid && half == 0) {
        float2 p = s_acc[wib + 1][lane];
        acc.x += p.x; acc.y += p.y;
        denom += s_den[wib + 1][lane];

        float inv = 1.f / (denom + 1e-9f);
        float2 b2 = *(const float2*)(bias + lane * 2);
        float2 o;
        o.x = acc.x * inv + b2.x;
        o.y = acc.y * inv + b2.y;
        *(float2*)(out + (size_t)node * 64 + lane * 2) = o;
    }
}

// -----------------------------------------------------------------------------
extern "C" void kernel_launch(void* const* d_in, const int* in_sizes, int n_in,
                              void* d_out, int out_size) {
    const float* x   = (const float*)d_in[0];
    const void*  src = d_in[1];
    const void*  dst = d_in[2];
    const float* W1 = (const float*)d_in[3];
    const float* al1 = (const float*)d_in[4];
    const float* ar1 = (const float*)d_in[5];
    const float* b1 = (const float*)d_in[6];
    const float* W2 = (const float*)d_in[7];
    const float* al2 = (const float*)d_in[8];
    const float* ar2 = (const float*)d_in[9];
    const float* b2 = (const float*)d_in[10];
    const float* W3 = (const float*)d_in[11];
    const float* al3 = (const float*)d_in[12];
    const float* ar3 = (const float*)d_in[13];
    const float* b3 = (const float*)d_in[14];
    float* out = (float*)d_out;

    const int n_nodes = NNODES;
    const int n_edges = in_sizes[1];

    detect_idx_kernel<<<1, 1024>>>((const int*)dst, n_edges);
    rowptr_kernel<<<(n_nodes + 1 + 255) / 256, 256>>>(dst, n_nodes, n_edges);

    const int gemm_blocks = (n_nodes + 127) / 128;
    const int agg_blocks = (n_nodes * 2 * 32 + 255) / 256;   // two warps per node

    float* feat; cudaGetSymbolAddress((void**)&feat, g_feat);
    float* hbuf; cudaGetSymbolAddress((void**)&hbuf, g_h);

    // ---- layer 1: 256 -> (4,32), ELU
    gemm_tc_kernel<256, 128, 4><<<gemm_blocks, 256>>>(x, W1, al1, ar1, feat, n_nodes);
    gat_agg128_kernel<true><<<agg_blocks, 256>>>(src, feat, b1, hbuf, n_nodes);

    // ---- layer 2: 128 -> (4,32), ELU
    gemm_tc_kernel<128, 128, 4><<<gemm_blocks, 256>>>(hbuf, W2, al2, ar2, feat, n_nodes);
    gat_agg128_kernel<true><<<agg_blocks, 256>>>(src, feat, b2, hbuf, n_nodes);

    // ---- layer 3: 128 -> (1,64), no activation; mean over 1 head == identity
    gemm_tc_kernel<128, 64, 1><<<gemm_blocks, 256>>>(hbuf, W3, al3, ar3, feat, n_nodes);
    gat_agg64_kernel<<<agg_blocks, 256>>>(src, feat, b3, out, n_nodes);
}

// round 17
// speedup vs baseline: 1.0547x; 1.0547x over previous
#include <cuda_runtime.h>
#include <cuda_fp16.h>
#include <math.h>

#define NNODES 50000
#define NEDGES 800000
#define NEG_SLOPE 0.2f

// ---------------- scratch (static device globals; no runtime allocation) ----
__device__ __half g_feat[NNODES * 128];   // projected features, fp16
__device__ float  g_h[NNODES * 128];      // layer activations, fp32 (GEMM input)
__device__ float  g_el[NNODES * 4];
__device__ float  g_er[NNODES * 4];
__device__ float  g_w[(size_t)NEDGES * 4];
__device__ int    g_rowptr[NNODES + 1];
__device__ int    g_idx64;

// ---------------- index dtype detection (tail scan) ---------------------------
__global__ void detect_idx_kernel(const int* __restrict__ words, int n_words) {
    __shared__ int any;
    if (threadIdx.x == 0) any = 0;
    __syncthreads();
    int base = n_words > 4096 ? (n_words - 4096) & ~1 : 0;
    int local = 0;
    for (int i = base + 2 * threadIdx.x + 1; i < n_words; i += 2 * blockDim.x)
        local |= words[i];
    if (local) atomicOr(&any, 1);
    __syncthreads();
    if (threadIdx.x == 0) g_idx64 = any ? 0 : 1;
}

__device__ __forceinline__ int load_idx(const void* p, int i, int is64) {
    if (is64) return (int)((const long long*)p)[i];
    return ((const int*)p)[i];
}

// ---------------- CSR row pointers from sorted dst ---------------------------
__global__ void __launch_bounds__(256) rowptr_kernel(const void* __restrict__ dst,
                                                     int n_nodes, int n_edges) {
    int n = blockIdx.x * blockDim.x + threadIdx.x;
    if (n > n_nodes) return;
    int is64 = g_idx64;
    int lo = 0, hi = n_edges;
    while (lo < hi) {
        int mid = (lo + hi) >> 1;
        if (load_idx(dst, mid, is64) < n) lo = mid + 1; else hi = mid;
    }
    g_rowptr[n] = lo;
}

// ---------------- tf32 helpers ------------------------------------------------
__device__ __forceinline__ float to_tf32(float x) {
    unsigned u;
    asm("cvt.rna.tf32.f32 %0, %1;" : "=r"(u) : "f"(x));
    return __uint_as_float(u);
}

__device__ __forceinline__ void mma_tf32(float* d, const unsigned* a, const unsigned* b) {
    asm volatile(
        "mma.sync.aligned.m16n8k8.row.col.f32.tf32.tf32.f32 "
        "{%0,%1,%2,%3}, {%4,%5,%6,%7}, {%8,%9}, {%0,%1,%2,%3};"
        : "+f"(d[0]), "+f"(d[1]), "+f"(d[2]), "+f"(d[3])
        : "r"(a[0]), "r"(a[1]), "r"(a[2]), "r"(a[3]), "r"(b[0]), "r"(b[1]));
}

// ---------------- tf32 tensor-core GEMM + fused el/er, fp16 C output ----------
template<int K, int MOUT, int H>
__global__ void __launch_bounds__(256) gemm_tc_kernel(const float* __restrict__ A,
                                                      const float* __restrict__ W,
                                                      const float* __restrict__ al,
                                                      const float* __restrict__ ar,
                                                      __half* __restrict__ C, int nrows) {
    constexpr int BM = 128, BK = 32;
    constexpr int AP = BM + 8;
    constexpr int BP = MOUT + 8;
    constexpr int WN = MOUT / 4;
    constexpr int NT = WN / 8;
    constexpr int MT = 4;

    __shared__ float As[BK * AP];
    __shared__ float Bs[BK * BP];
    __shared__ float elp[4][BM];
    __shared__ float erp[4][BM];

    int tid = threadIdx.x;
    int wid = tid >> 5;
    int lane = tid & 31;
    int wr = wid >> 2;
    int wc = wid & 3;
    int g = lane >> 2;
    int tig = lane & 3;
    int row0 = blockIdx.x * BM;
    int mwarp = wr * 64;

    float acc[MT][NT][4];
#pragma unroll
    for (int mt = 0; mt < MT; mt++)
#pragma unroll
        for (int nt = 0; nt < NT; nt++)
#pragma unroll
            for (int q = 0; q < 4; q++) acc[mt][nt][q] = 0.f;

    for (int kb = 0; kb < K; kb += BK) {
#pragma unroll
        for (int l = 0; l < (BM * BK) / (256 * 4); ++l) {
            int idx = (tid + l * 256) * 4;
            int r = idx / BK, c = idx % BK;
            float4 v = make_float4(0.f, 0.f, 0.f, 0.f);
            int gr = row0 + r;
            if (gr < nrows) v = *(const float4*)(A + (size_t)gr * K + kb + c);
            v.x = to_tf32(v.x); v.y = to_tf32(v.y); v.z = to_tf32(v.z); v.w = to_tf32(v.w);
            As[(c + 0) * AP + (r ^ ((((c + 0) >> 2) & 7) << 2))] = v.x;
            As[(c + 1) * AP + (r ^ ((((c + 1) >> 2) & 7) << 2))] = v.y;
            As[(c + 2) * AP + (r ^ ((((c + 2) >> 2) & 7) << 2))] = v.z;
            As[(c + 3) * AP + (r ^ ((((c + 3) >> 2) & 7) << 2))] = v.w;
        }
#pragma unroll
        for (int l = 0; l < (BK * MOUT) / (256 * 4); ++l) {
            int idx = (tid + l * 256) * 4;
            int r = idx / MOUT, c = idx % MOUT;
            float4 v = *(const float4*)(W + (size_t)(kb + r) * MOUT + c);
            v.x = to_tf32(v.x); v.y = to_tf32(v.y); v.z = to_tf32(v.z); v.w = to_tf32(v.w);
            *(float4*)&Bs[r * BP + c] = v;
        }
        __syncthreads();

#pragma unroll
        for (int ks = 0; ks < BK / 8; ks++) {
            int k0 = ks * 8;
            int ka = k0 + tig, kc = k0 + tig + 4;
            int sa = ((ka >> 2) & 7) << 2;
            int sc = ((kc >> 2) & 7) << 2;
            unsigned af[MT][4];
#pragma unroll
            for (int mt = 0; mt < MT; mt++) {
                int mb = mwarp + mt * 16;
                af[mt][0] = __float_as_uint(As[ka * AP + ((mb + g)     ^ sa)]);
                af[mt][1] = __float_as_uint(As[ka * AP + ((mb + g + 8) ^ sa)]);
                af[mt][2] = __float_as_uint(As[kc * AP + ((mb + g)     ^ sc)]);
                af[mt][3] = __float_as_uint(As[kc * AP + ((mb + g + 8) ^ sc)]);
            }
            unsigned bf[NT][2];
#pragma unroll
            for (int nt = 0; nt < NT; nt++) {
                int nb = wc * WN + nt * 8 + g;
                bf[nt][0] = __float_as_uint(Bs[ka * BP + nb]);
                bf[nt][1] = __float_as_uint(Bs[kc * BP + nb]);
            }
#pragma unroll
            for (int mt = 0; mt < MT; mt++)
#pragma unroll
                for (int nt = 0; nt < NT; nt++)
                    mma_tf32(acc[mt][nt], af[mt], bf[nt]);
        }
        __syncthreads();
    }

#pragma unroll
    for (int mt = 0; mt < MT; mt++) {
        int lr0 = mwarp + mt * 16 + g;
        int gr0 = row0 + lr0, gr1 = gr0 + 8;
        float sl0 = 0.f, sr0 = 0.f, sl1 = 0.f, sr1 = 0.f;
#pragma unroll
        for (int nt = 0; nt < NT; nt++) {
            int c = wc * WN + nt * 8 + 2 * tig;
            float a0 = al[c], a1 = al[c + 1];
            float r0 = ar[c], r1 = ar[c + 1];
            float* d = acc[mt][nt];
            sl0 += d[0] * a0 + d[1] * a1;  sr0 += d[0] * r0 + d[1] * r1;
            sl1 += d[2] * a0 + d[3] * a1;  sr1 += d[2] * r0 + d[3] * r1;
            if (gr0 < nrows)
                *(__half2*)(C + (size_t)gr0 * MOUT + c) = __floats2half2_rn(d[0], d[1]);
            if (gr1 < nrows)
                *(__half2*)(C + (size_t)gr1 * MOUT + c) = __floats2half2_rn(d[2], d[3]);
        }
#pragma unroll
        for (int off = 1; off <= 2; off <<= 1) {
            sl0 += __shfl_xor_sync(0xFFFFFFFFu, sl0, off);
            sr0 += __shfl_xor_sync(0xFFFFFFFFu, sr0, off);
            sl1 += __shfl_xor_sync(0xFFFFFFFFu, sl1, off);
            sr1 += __shfl_xor_sync(0xFFFFFFFFu, sr1, off);
        }
        if (tig == 0) {
            elp[wc][lr0] = sl0;  elp[wc][lr0 + 8] = sl1;
            erp[wc][lr0] = sr0;  erp[wc][lr0 + 8] = sr1;
        }
    }
    __syncthreads();
    if (tid < BM) {
        int gr = row0 + tid;
        if (gr < nrows) {
            if (H == 4) {
                *(float4*)(g_el + gr * 4) =
                    make_float4(elp[0][tid], elp[1][tid], elp[2][tid], elp[3][tid]);
                *(float4*)(g_er + gr * 4) =
                    make_float4(erp[0][tid], erp[1][tid], erp[2][tid], erp[3][tid]);
            } else {
                g_el[gr] = elp[0][tid] + elp[1][tid] + elp[2][tid] + elp[3][tid];
                g_er[gr] = erp[0][tid] + erp[1][tid] + erp[2][tid] + erp[3][tid];
            }
        }
    }
}

// ---------------- edge weights: w[e,h] = exp(leaky(el[src]+er[dst])) ----------
template<int H>
__global__ void __launch_bounds__(256) edge_w_kernel(const void* __restrict__ src,
                                                     const void* __restrict__ dst,
                                                     int n_edges) {
    int e = blockIdx.x * blockDim.x + threadIdx.x;
    if (e >= n_edges) return;
    int is64 = g_idx64;
    int s = load_idx(src, e, is64);
    int d = load_idx(dst, e, is64);
    if (H == 4) {
        float4 l = *(const float4*)(g_el + s * 4);
        float4 r = *(const float4*)(g_er + d * 4);
        float4 w; float t;
        t = l.x + r.x; t = (t > 0.f) ? t : NEG_SLOPE * t; w.x = __expf(t);
        t = l.y + r.y; t = (t > 0.f) ? t : NEG_SLOPE * t; w.y = __expf(t);
        t = l.z + r.z; t = (t > 0.f) ? t : NEG_SLOPE * t; w.z = __expf(t);
        t = l.w + r.w; t = (t > 0.f) ? t : NEG_SLOPE * t; w.w = __expf(t);
        *(float4*)(g_w + (size_t)e * 4) = w;
    } else {
        float t = g_el[s] + g_er[d];
        t = (t > 0.f) ? t : NEG_SLOPE * t;
        g_w[e] = __expf(t);
    }
}

// ---------------- aggregation, H=4 D=32: two warps/node, fp16 feat ------------
template<bool DO_ELU>
__global__ void __launch_bounds__(256) gat_agg128_kernel(const void* __restrict__ src,
                                                         const __half* __restrict__ feat,
                                                         const float* __restrict__ bias,
                                                         float* __restrict__ out, int n_nodes) {
    __shared__ float4 s_acc[8][32];
    __shared__ float  s_den[8][32];

    int gw = (blockIdx.x * blockDim.x + threadIdx.x) >> 5;
    int wib = threadIdx.x >> 5;
    int lane = threadIdx.x & 31;
    int node = gw >> 1;
    int half = gw & 1;
    bool valid = node < n_nodes;
    int is64 = g_idx64;
    int hh = lane >> 3;

    float4 acc = make_float4(0.f, 0.f, 0.f, 0.f);
    float denom = 0.f;

    if (valid) {
        int start = g_rowptr[node];
        int end = g_rowptr[node + 1];
        int i = start + half;
        for (; i + 14 < end; i += 16) {
            int s[8]; float w[8]; uint2 raw[8];
#pragma unroll
            for (int j = 0; j < 8; j++) s[j] = load_idx(src, i + 2 * j, is64);
#pragma unroll
            for (int j = 0; j < 8; j++) w[j] = g_w[(size_t)(i + 2 * j) * 4 + hh];
#pragma unroll
            for (int j = 0; j < 8; j++)
                raw[j] = *(const uint2*)(feat + (size_t)s[j] * 128 + lane * 4);
#pragma unroll
            for (int j = 0; j < 8; j++) {
                float2 f0 = __half22float2(*reinterpret_cast<__half2*>(&raw[j].x));
                float2 f1 = __half22float2(*reinterpret_cast<__half2*>(&raw[j].y));
                denom += w[j];
                acc.x += w[j] * f0.x; acc.y += w[j] * f0.y;
                acc.z += w[j] * f1.x; acc.w += w[j] * f1.y;
            }
        }
        for (; i + 6 < end; i += 8) {
            int s[4]; float w[4]; uint2 raw[4];
#pragma unroll
            for (int j = 0; j < 4; j++) s[j] = load_idx(src, i + 2 * j, is64);
#pragma unroll
            for (int j = 0; j < 4; j++) w[j] = g_w[(size_t)(i + 2 * j) * 4 + hh];
#pragma unroll
            for (int j = 0; j < 4; j++)
                raw[j] = *(const uint2*)(feat + (size_t)s[j] * 128 + lane * 4);
#pragma unroll
            for (int j = 0; j < 4; j++) {
                float2 f0 = __half22float2(*reinterpret_cast<__half2*>(&raw[j].x));
                float2 f1 = __half22float2(*reinterpret_cast<__half2*>(&raw[j].y));
                denom += w[j];
                acc.x += w[j] * f0.x; acc.y += w[j] * f0.y;
                acc.z += w[j] * f1.x; acc.w += w[j] * f1.y;
            }
        }
        for (; i < end; i += 2) {
            int s = load_idx(src, i, is64);
            float w = g_w[(size_t)i * 4 + hh];
            uint2 raw = *(const uint2*)(feat + (size_t)s * 128 + lane * 4);
            float2 f0 = __half22float2(*reinterpret_cast<__half2*>(&raw.x));
            float2 f1 = __half22float2(*reinterpret_cast<__half2*>(&raw.y));
            denom += w;
            acc.x += w * f0.x; acc.y += w * f0.y;
            acc.z += w * f1.x; acc.w += w * f1.y;
        }
    }

    if (half == 1) { s_acc[wib][lane] = acc; s_den[wib][lane] = denom; }
    __syncthreads();

    if (valid && half == 0) {
        float4 p = s_acc[wib + 1][lane];
        acc.x += p.x; acc.y += p.y; acc.z += p.z; acc.w += p.w;
        denom += s_den[wib + 1][lane];

        float inv = 1.f / (denom + 1e-9f);
        float4 b4 = *(const float4*)(bias + lane * 4);
        float4 o;
        o.x = acc.x * inv + b4.x;
        o.y = acc.y * inv + b4.y;
        o.z = acc.z * inv + b4.z;
        o.w = acc.w * inv + b4.w;
        if (DO_ELU) {
            o.x = (o.x > 0.f) ? o.x : expm1f(o.x);
            o.y = (o.y > 0.f) ? o.y : expm1f(o.y);
            o.z = (o.z > 0.f) ? o.z : expm1f(o.z);
            o.w = (o.w > 0.f) ? o.w : expm1f(o.w);
        }
        *(float4*)(out + (size_t)node * 128 + lane * 4) = o;
    }
}

// ---------------- aggregation, H=1 D=64: two warps/node, fp16 feat ------------
__global__ void __launch_bounds__(256) gat_agg64_kernel(const void* __restrict__ src,
                                                        const __half* __restrict__ feat,
                                                        const float* __restrict__ bias,
                                                        float* __restrict__ out, int n_nodes) {
    __shared__ float2 s_acc[8][32];
    __shared__ float  s_den[8][32];

    int gw = (blockIdx.x * blockDim.x + threadIdx.x) >> 5;
    int wib = threadIdx.x >> 5;
    int lane = threadIdx.x & 31;
    int node = gw >> 1;
    int half = gw & 1;
    bool valid = node < n_nodes;
    int is64 = g_idx64;

    float2 acc = make_float2(0.f, 0.f);
    float denom = 0.f;

    if (valid) {
        int start = g_rowptr[node];
        int end = g_rowptr[node + 1];
        int i = start + half;
        for (; i + 14 < end; i += 16) {
            int s[8]; float w[8]; unsigned raw[8];
#pragma unroll
            for (int j = 0; j < 8; j++) s[j] = load_idx(src, i + 2 * j, is64);
#pragma unroll
            for (int j = 0; j < 8; j++) w[j] = g_w[i + 2 * j];
#pragma unroll
            for (int j = 0; j < 8; j++)
                raw[j] = *(const unsigned*)(feat + (size_t)s[j] * 64 + lane * 2);
#pragma unroll
            for (int j = 0; j < 8; j++) {
                float2 f = __half22float2(*reinterpret_cast<__half2*>(&raw[j]));
                denom += w[j];
                acc.x += w[j] * f.x; acc.y += w[j] * f.y;
            }
        }
        for (; i + 6 < end; i += 8) {
            int s[4]; float w[4]; unsigned raw[4];
#pragma unroll
            for (int j = 0; j < 4; j++) s[j] = load_idx(src, i + 2 * j, is64);
#pragma unroll
            for (int j = 0; j < 4; j++) w[j] = g_w[i + 2 * j];
#pragma unroll
            for (int j = 0; j < 4; j++)
                raw[j] = *(const unsigned*)(feat + (size_t)s[j] * 64 + lane * 2);
#pragma unroll
            for (int j = 0; j < 4; j++) {
                float2 f = __half22float2(*reinterpret_cast<__half2*>(&raw[j]));
                denom += w[j];
                acc.x += w[j] * f.x; acc.y += w[j] * f.y;
            }
        }
        for (; i < end; i += 2) {
            int s = load_idx(src, i, is64);
            float w = g_w[i];
            unsigned raw = *(const unsigned*)(feat + (size_t)s * 64 + lane * 2);
            float2 f = __half22float2(*reinterpret_cast<__half2*>(&raw));
            denom += w;
            acc.x += w * f.x; acc.y += w * f.y;
        }
    }

    if (half == 1) { s_acc[wib][lane] = acc; s_den[wib][lane] = denom; }
    __syncthreads();

    if (valid && half == 0) {
        float2 p = s_acc[wib + 1][lane];
        acc.x += p.x; acc.y += p.y;
        denom += s_den[wib + 1][lane];

        float inv = 1.f / (denom + 1e-9f);
        float2 b2 = *(const float2*)(bias + lane * 2);
        float2 o;
        o.x = acc.x * inv + b2.x;
        o.y = acc.y * inv + b2.y;
        *(float2*)(out + (size_t)node * 64 + lane * 2) = o;
    }
}

// -----------------------------------------------------------------------------
extern "C" void kernel_launch(void* const* d_in, const int* in_sizes, int n_in,
                              void* d_out, int out_size) {
    const float* x   = (const float*)d_in[0];
    const void*  src = d_in[1];
    const void*  dst = d_in[2];
    const float* W1 = (const float*)d_in[3];
    const float* al1 = (const float*)d_in[4];
    const float* ar1 = (const float*)d_in[5];
    const float* b1 = (const float*)d_in[6];
    const float* W2 = (const float*)d_in[7];
    const float* al2 = (const float*)d_in[8];
    const float* ar2 = (const float*)d_in[9];
    const float* b2 = (const float*)d_in[10];
    const float* W3 = (const float*)d_in[11];
    const float* al3 = (const float*)d_in[12];
    const float* ar3 = (const float*)d_in[13];
    const float* b3 = (const float*)d_in[14];
    float* out = (float*)d_out;

    const int n_nodes = NNODES;
    const int n_edges = in_sizes[1];

    detect_idx_kernel<<<1, 1024>>>((const int*)dst, n_edges);
    rowptr_kernel<<<(n_nodes + 1 + 255) / 256, 256>>>(dst, n_nodes, n_edges);

    const int gemm_blocks = (n_nodes + 127) / 128;
    const int agg_blocks = (n_nodes * 2 * 32 + 255) / 256;   // two warps per node
    const int edge_blocks = (n_edges + 255) / 256;           // one edge per thread

    __half* feat; cudaGetSymbolAddress((void**)&feat, g_feat);
    float* hbuf;  cudaGetSymbolAddress((void**)&hbuf, g_h);

    // ---- layer 1: 256 -> (4,32), ELU
    gemm_tc_kernel<256, 128, 4><<<gemm_blocks, 256>>>(x, W1, al1, ar1, feat, n_nodes);
    edge_w_kernel<4><<<edge_blocks, 256>>>(src, dst, n_edges);
    gat_agg128_kernel<true><<<agg_blocks, 256>>>(src, feat, b1, hbuf, n_nodes);

    // ---- layer 2: 128 -> (4,32), ELU
    gemm_tc_kernel<128, 128, 4><<<gemm_blocks, 256>>>(hbuf, W2, al2, ar2, feat, n_nodes);
    edge_w_kernel<4><<<edge_blocks, 256>>>(src, dst, n_edges);
    gat_agg128_kernel<true><<<agg_blocks, 256>>>(src, feat, b2, hbuf, n_nodes);

    // ---- layer 3: 128 -> (1,64), no activation; mean over 1 head == identity
    gemm_tc_kernel<128, 64, 1><<<gemm_blocks, 256>>>(hbuf, W3, al3, ar3, feat, n_nodes);
    edge_w_kernel<1><<<edge_blocks, 256>>>(src, dst, n_edges);
    gat_agg64_kernel<<<agg_blocks, 256>>>(src, feat, b3, out, n_nodes);
}